// round 3
// baseline (speedup 1.0000x reference)
#include <cuda_runtime.h>

#define INPUT_SIZE   32768
#define NUM_COLS     4096
#define NUM_ACTIVE   82

// Scratch (allocation-free rule: __device__ globals)
__device__ int   g_count;
__device__ int   g_indices[INPUT_SIZE];
__device__ float g_boosted[NUM_COLS];

// ---------------------------------------------------------------------------
// Kernel 1: ordered compaction of on-bit indices of input_vector.
// 1 block, 1024 threads, each thread owns 32 contiguous elements (so the
// compacted index list stays globally sorted -> good DRAM locality for the
// gathers in kernel 2).
// ---------------------------------------------------------------------------
__global__ __launch_bounds__(1024, 1)
void compact_kernel(const float* __restrict__ in) {
    const int t    = threadIdx.x;       // 0..1023
    const int base = t * 32;

    // Load my 32 contiguous floats (8x float4, vectorized).
    float v[32];
    const float4* p = reinterpret_cast<const float4*>(in + base);
#pragma unroll
    for (int i = 0; i < 8; i++) {
        float4 q = p[i];
        v[4*i+0] = q.x; v[4*i+1] = q.y; v[4*i+2] = q.z; v[4*i+3] = q.w;
    }

    int cnt = 0;
#pragma unroll
    for (int i = 0; i < 32; i++) cnt += (v[i] != 0.0f) ? 1 : 0;

    // Block-wide exclusive scan of per-thread counts (32 warps).
    const int lane = t & 31, warp = t >> 5;
    int x = cnt;
#pragma unroll
    for (int d = 1; d < 32; d <<= 1) {
        int y = __shfl_up_sync(0xffffffffu, x, d);
        if (lane >= d) x += y;            // x = inclusive warp scan
    }
    __shared__ int wsum[32];
    if (lane == 31) wsum[warp] = x;
    __syncthreads();
    if (warp == 0) {
        int w = wsum[lane];
#pragma unroll
        for (int d = 1; d < 32; d <<= 1) {
            int y = __shfl_up_sync(0xffffffffu, w, d);
            if (lane >= d) w += y;
        }
        wsum[lane] = w;                   // inclusive scan of warp totals
    }
    __syncthreads();

    int off = (x - cnt) + (warp ? wsum[warp - 1] : 0);   // exclusive prefix
#pragma unroll
    for (int i = 0; i < 32; i++) {
        if (v[i] != 0.0f) g_indices[off++] = base + i;
    }
    if (t == 1023) g_count = off;         // thread 1023 ends at the total
}

// ---------------------------------------------------------------------------
// Kernel 2: sparse matvec. One block per minicolumn row; 128 threads gather
// connections[c, idx[k]] over the active-index list, block-reduce, boost.
// Sums are exact small integers -> order-independent, bit-exact vs reference.
// ---------------------------------------------------------------------------
__global__ __launch_bounds__(128)
void matvec_sparse_kernel(const float* __restrict__ conn,
                          const float* __restrict__ boost) {
    const int c = blockIdx.x;
    const float* __restrict__ row = conn + (size_t)c * INPUT_SIZE;
    const int n = g_count;

    float s = 0.0f;
    for (int k = threadIdx.x; k < n; k += 128) {
        s += __ldg(row + __ldg(&g_indices[k]));
    }

    // Block reduce (4 warps).
#pragma unroll
    for (int d = 16; d; d >>= 1) s += __shfl_down_sync(0xffffffffu, s, d);

    __shared__ float ws[4];
    const int lane = threadIdx.x & 31, warp = threadIdx.x >> 5;
    if (lane == 0) ws[warp] = s;
    __syncthreads();
    if (threadIdx.x == 0) {
        float tot = ws[0] + ws[1] + ws[2] + ws[3];
        g_boosted[c] = tot * __ldg(&boost[c]);
    }
}

// ---------------------------------------------------------------------------
// Kernel 3: stable top-k by exact rank counting (matches jax.lax.top_k
// tie-break: lower index wins among equal values). One warp per column.
// Writes both output segments: [0,4096) active mask, [4096,8192) masked value.
// ---------------------------------------------------------------------------
__global__ __launch_bounds__(256)
void topk_rank_kernel(float* __restrict__ out) {
    const int warp = threadIdx.x >> 5;
    const int lane = threadIdx.x & 31;
    const int c    = blockIdx.x * 8 + warp;

    const float vc = g_boosted[c];
    int cnt = 0;
#pragma unroll 4
    for (int j = lane; j < NUM_COLS; j += 32) {
        float v = __ldg(&g_boosted[j]);
        cnt += ((v > vc) || (v == vc && j < c)) ? 1 : 0;
    }
#pragma unroll
    for (int d = 16; d; d >>= 1) cnt += __shfl_down_sync(0xffffffffu, cnt, d);

    if (lane == 0) {
        const bool win = (cnt < NUM_ACTIVE);
        out[c]            = win ? 1.0f : 0.0f;
        out[NUM_COLS + c] = win ? vc   : 0.0f;
    }
}

// ---------------------------------------------------------------------------
extern "C" void kernel_launch(void* const* d_in, const int* in_sizes, int n_in,
                              void* d_out, int out_size) {
    // Identify inputs by element count (robust to metadata ordering):
    //   input_vector: 32768, connections: 4096*32768, boosting_factors: 4096.
    const float* inp   = nullptr;
    const float* conn  = nullptr;
    const float* boost = nullptr;
    for (int i = 0; i < n_in; i++) {
        if (in_sizes[i] == INPUT_SIZE)      inp   = (const float*)d_in[i];
        else if (in_sizes[i] == NUM_COLS)   boost = (const float*)d_in[i];
        else                                conn  = (const float*)d_in[i];
    }
    float* out = (float*)d_out;
    (void)out_size; (void)n_in;

    compact_kernel<<<1, 1024>>>(inp);
    matvec_sparse_kernel<<<NUM_COLS, 128>>>(conn, boost);
    topk_rank_kernel<<<NUM_COLS / 8, 256>>>(out);
}

// round 4
// speedup vs baseline: 1.0630x; 1.0630x over previous
#include <cuda_runtime.h>

#define INPUT_SIZE   32768
#define NUM_COLS     4096
#define NUM_ACTIVE   82
#define MAX_IDX      INPUT_SIZE

// Scratch (allocation-free rule: __device__ globals; zero-initialized at load)
__device__ int   g_count;
__device__ int   g_indices[MAX_IDX];
__device__ float g_boosted[NUM_COLS];

// ---------------------------------------------------------------------------
// Kernel 1: parallel compaction of on-bit indices. 32 blocks x 256 threads,
// each block owns a contiguous 1024-element chunk, compacts locally (sorted
// within the chunk), and reserves its output slice via one atomicAdd.
// Global run order is nondeterministic, but the downstream sum is an exact
// small-integer commutative reduction -> output is invariant.
// g_count must be 0 on entry: zero-init on first run, reset by topk tail after.
// ---------------------------------------------------------------------------
__global__ __launch_bounds__(256, 4)
void compact_kernel(const float* __restrict__ in) {
    const int t    = threadIdx.x;                    // 0..255
    const int base = blockIdx.x * 1024 + t * 4;

    float4 q = reinterpret_cast<const float4*>(in)[base >> 2];
    float v[4] = {q.x, q.y, q.z, q.w};

    int cnt = 0;
#pragma unroll
    for (int i = 0; i < 4; i++) cnt += (v[i] != 0.0f) ? 1 : 0;

    // Block scan over 8 warps.
    const int lane = t & 31, warp = t >> 5;
    int x = cnt;
#pragma unroll
    for (int d = 1; d < 32; d <<= 1) {
        int y = __shfl_up_sync(0xffffffffu, x, d);
        if (lane >= d) x += y;                       // inclusive warp scan
    }
    __shared__ int wsum[8];
    __shared__ int sbase;
    if (lane == 31) wsum[warp] = x;
    __syncthreads();
    if (t == 0) {
        int acc = 0;
#pragma unroll
        for (int w = 0; w < 8; w++) { int c = wsum[w]; wsum[w] = acc; acc += c; }
        sbase = atomicAdd(&g_count, acc);            // reserve slice
    }
    __syncthreads();

    int off = sbase + wsum[warp] + (x - cnt);        // exclusive prefix
#pragma unroll
    for (int i = 0; i < 4; i++) {
        if (v[i] != 0.0f) g_indices[off++] = base + i;
    }
}

// ---------------------------------------------------------------------------
// Kernel 2: sparse matvec. One block per minicolumn row; 256 threads.
// Index list staged into SMEM once (breaks the idx->gather dependent chain),
// then a 4-way unrolled gather loop with streaming loads (no reuse).
// Lanes take consecutive sorted indices -> coalesced warp gathers.
// ---------------------------------------------------------------------------
__global__ __launch_bounds__(256, 8)
void matvec_sparse_kernel(const float* __restrict__ conn,
                          const float* __restrict__ boost) {
    __shared__ int sidx[2048];                       // >= expected ~1638, 8KB
    const int c   = blockIdx.x;
    const int tid = threadIdx.x;
    const int n   = g_count;

    for (int k = tid; k < n; k += 256) sidx[k] = g_indices[k];
    __syncthreads();

    const float* __restrict__ row = conn + (size_t)c * INPUT_SIZE;

    float s0 = 0.0f, s1 = 0.0f, s2 = 0.0f, s3 = 0.0f;
    int k = tid;
    for (; k + 768 < n; k += 1024) {
        int i0 = sidx[k], i1 = sidx[k + 256], i2 = sidx[k + 512], i3 = sidx[k + 768];
        s0 += __ldcs(row + i0);
        s1 += __ldcs(row + i1);
        s2 += __ldcs(row + i2);
        s3 += __ldcs(row + i3);
    }
    for (; k < n; k += 256) s0 += __ldcs(row + sidx[k]);
    float s = (s0 + s1) + (s2 + s3);

    // Block reduce (8 warps).
#pragma unroll
    for (int d = 16; d; d >>= 1) s += __shfl_down_sync(0xffffffffu, s, d);
    __shared__ float ws[8];
    const int lane = tid & 31, warp = tid >> 5;
    if (lane == 0) ws[warp] = s;
    __syncthreads();
    if (tid == 0) {
        float tot = 0.0f;
#pragma unroll
        for (int w = 0; w < 8; w++) tot += ws[w];
        g_boosted[c] = tot * __ldg(&boost[c]);
    }
}

// ---------------------------------------------------------------------------
// Kernel 3: stable top-k by exact rank counting (matches jax.lax.top_k
// tie-break: lower index wins among equal values). One warp per column.
// Also resets g_count for the next graph replay (matvec of THIS run already
// consumed it; in-stream ordering makes this safe).
// ---------------------------------------------------------------------------
__global__ __launch_bounds__(256)
void topk_rank_kernel(float* __restrict__ out) {
    if (blockIdx.x == 0 && threadIdx.x == 0) g_count = 0;

    const int warp = threadIdx.x >> 5;
    const int lane = threadIdx.x & 31;
    const int c    = blockIdx.x * 8 + warp;

    const float vc = g_boosted[c];
    int cnt = 0;
#pragma unroll 4
    for (int j = lane; j < NUM_COLS; j += 32) {
        float v = __ldg(&g_boosted[j]);
        cnt += ((v > vc) || (v == vc && j < c)) ? 1 : 0;
    }
#pragma unroll
    for (int d = 16; d; d >>= 1) cnt += __shfl_down_sync(0xffffffffu, cnt, d);

    if (lane == 0) {
        const bool win = (cnt < NUM_ACTIVE);
        out[c]            = win ? 1.0f : 0.0f;
        out[NUM_COLS + c] = win ? vc   : 0.0f;
    }
}

// ---------------------------------------------------------------------------
extern "C" void kernel_launch(void* const* d_in, const int* in_sizes, int n_in,
                              void* d_out, int out_size) {
    const float* inp   = nullptr;
    const float* conn  = nullptr;
    const float* boost = nullptr;
    for (int i = 0; i < n_in; i++) {
        if (in_sizes[i] == INPUT_SIZE)      inp   = (const float*)d_in[i];
        else if (in_sizes[i] == NUM_COLS)   boost = (const float*)d_in[i];
        else                                conn  = (const float*)d_in[i];
    }
    float* out = (float*)d_out;
    (void)out_size; (void)n_in;

    compact_kernel<<<32, 256>>>(inp);
    matvec_sparse_kernel<<<NUM_COLS, 256>>>(conn, boost);
    topk_rank_kernel<<<NUM_COLS / 8, 256>>>(out);
}

// round 5
// speedup vs baseline: 1.1231x; 1.0566x over previous
#include <cuda_runtime.h>

#define INPUT_SIZE     32768
#define NUM_COLS       4096
#define NUM_ACTIVE     82
#define THREADS        256
#define ROWS_PER_BLOCK 2
#define NBLOCKS        (NUM_COLS / ROWS_PER_BLOCK)   // 2048
#define COMPACT_BLOCKS 32
#define SMEM_IDX_CAP   4096

// Scratch (allocation-free rule). Zero-initialized at module load; reset by
// topk_kernel each call so graph replays stay deterministic.
__device__ int          g_count;
__device__ volatile int g_ready;
__device__ int          g_indices[INPUT_SIZE];
__device__ float        g_boosted[NUM_COLS];

// ---------------------------------------------------------------------------
// Fused kernel: blocks 0..31 compact the on-bit indices of input_vector
// (atomic slice reservation -> order nondeterministic, output invariant since
// all downstream sums are exact small-integer commutative reductions), all
// blocks then wait on a flag and run the sparse matvec for 2 rows each.
// ---------------------------------------------------------------------------
__global__ __launch_bounds__(THREADS, 8)
void fused_kernel(const float* __restrict__ in,
                  const float* __restrict__ conn,
                  const float* __restrict__ boost) {
    __shared__ int   sidx[SMEM_IDX_CAP];
    __shared__ int   s_n;
    __shared__ int   wsum[8];
    __shared__ int   sbase;
    __shared__ float wred[16];

    const int tid  = threadIdx.x;
    const int bid  = blockIdx.x;
    const int lane = tid & 31;
    const int warp = tid >> 5;

    // ---- Phase A: compaction (blocks 0..31; all are wave-1 resident) ----
    if (bid < COMPACT_BLOCKS) {
        const int base = bid * 1024 + tid * 4;
        float4 q = reinterpret_cast<const float4*>(in)[base >> 2];
        float v[4] = {q.x, q.y, q.z, q.w};
        int cnt = 0;
#pragma unroll
        for (int i = 0; i < 4; i++) cnt += (v[i] != 0.0f) ? 1 : 0;

        int x = cnt;
#pragma unroll
        for (int d = 1; d < 32; d <<= 1) {
            int y = __shfl_up_sync(0xffffffffu, x, d);
            if (lane >= d) x += y;                    // inclusive warp scan
        }
        if (lane == 31) wsum[warp] = x;
        __syncthreads();
        if (tid == 0) {
            int acc = 0;
#pragma unroll
            for (int w = 0; w < 8; w++) { int c = wsum[w]; wsum[w] = acc; acc += c; }
            sbase = atomicAdd(&g_count, acc);         // reserve output slice
        }
        __syncthreads();
        int off = sbase + wsum[warp] + (x - cnt);
#pragma unroll
        for (int i = 0; i < 4; i++)
            if (v[i] != 0.0f) g_indices[off++] = base + i;
        __threadfence();
        if (tid == 0) atomicAdd((int*)&g_ready, 1);
    }

    // ---- Wait for compaction to complete (flag in L2, coherent) ----
    if (tid == 0) {
        while (*(volatile int*)&g_ready < COMPACT_BLOCKS) __nanosleep(64);
        __threadfence();
        s_n = *(volatile int*)&g_count;
    }
    __syncthreads();
    const int n = s_n;

    // ---- Stage index list into SMEM (breaks idx->gather dependent chain) ----
    const int n_s = (n < SMEM_IDX_CAP) ? n : SMEM_IDX_CAP;
    for (int k = tid; k < n_s; k += THREADS) sidx[k] = g_indices[k];
    __syncthreads();

    // ---- Phase B: gather 2 rows with 8 independent load streams ----
    const int r = bid * ROWS_PER_BLOCK;
    const float* __restrict__ row0 = conn + (size_t)r * INPUT_SIZE;
    const float* __restrict__ row1 = row0 + INPUT_SIZE;

    float a0 = 0.f, a1 = 0.f, a2 = 0.f, a3 = 0.f;   // row0 accumulators
    float b0 = 0.f, b1 = 0.f, b2 = 0.f, b3 = 0.f;   // row1 accumulators
    int k = tid;
    for (; k + 3 * THREADS < n_s; k += 4 * THREADS) {
        int i0 = sidx[k];
        int i1 = sidx[k +     THREADS];
        int i2 = sidx[k + 2 * THREADS];
        int i3 = sidx[k + 3 * THREADS];
        a0 += __ldcs(row0 + i0);  b0 += __ldcs(row1 + i0);
        a1 += __ldcs(row0 + i1);  b1 += __ldcs(row1 + i1);
        a2 += __ldcs(row0 + i2);  b2 += __ldcs(row1 + i2);
        a3 += __ldcs(row0 + i3);  b3 += __ldcs(row1 + i3);
    }
    for (; k < n_s; k += THREADS) {
        int i = sidx[k];
        a0 += __ldcs(row0 + i);  b0 += __ldcs(row1 + i);
    }
    for (int k2 = SMEM_IDX_CAP + tid; k2 < n; k2 += THREADS) {  // safety tail
        int i = g_indices[k2];
        a0 += __ldcs(row0 + i);  b0 += __ldcs(row1 + i);
    }
    float sa = (a0 + a1) + (a2 + a3);
    float sb = (b0 + b1) + (b2 + b3);

    // ---- Block reduce both rows ----
#pragma unroll
    for (int d = 16; d; d >>= 1) {
        sa += __shfl_down_sync(0xffffffffu, sa, d);
        sb += __shfl_down_sync(0xffffffffu, sb, d);
    }
    if (lane == 0) { wred[warp] = sa; wred[8 + warp] = sb; }
    __syncthreads();
    if (tid == 0) {
        float ta = 0.f, tb = 0.f;
#pragma unroll
        for (int w = 0; w < 8; w++) { ta += wred[w]; tb += wred[8 + w]; }
        g_boosted[r]     = ta * __ldg(&boost[r]);
        g_boosted[r + 1] = tb * __ldg(&boost[r + 1]);
    }
}

// ---------------------------------------------------------------------------
// Stable top-k by exact rank counting (matches jax.lax.top_k tie-break:
// lower index wins among equal values). One warp per column, float4 scans.
// Also resets scratch flags for the next graph replay.
// ---------------------------------------------------------------------------
__global__ __launch_bounds__(256)
void topk_kernel(float* __restrict__ out) {
    if (blockIdx.x == 0 && threadIdx.x == 0) { g_count = 0; g_ready = 0; }

    const int warp = threadIdx.x >> 5;
    const int lane = threadIdx.x & 31;
    const int c    = blockIdx.x * 8 + warp;

    const float vc = g_boosted[c];
    int cnt = 0;
    const float4* gb4 = reinterpret_cast<const float4*>(g_boosted);
#pragma unroll 4
    for (int q = lane; q < NUM_COLS / 4; q += 32) {
        float4 v = __ldg(&gb4[q]);
        int j = q * 4;
        cnt += ((v.x > vc) || (v.x == vc && j     < c)) ? 1 : 0;
        cnt += ((v.y > vc) || (v.y == vc && j + 1 < c)) ? 1 : 0;
        cnt += ((v.z > vc) || (v.z == vc && j + 2 < c)) ? 1 : 0;
        cnt += ((v.w > vc) || (v.w == vc && j + 3 < c)) ? 1 : 0;
    }
#pragma unroll
    for (int d = 16; d; d >>= 1) cnt += __shfl_down_sync(0xffffffffu, cnt, d);

    if (lane == 0) {
        const bool win = (cnt < NUM_ACTIVE);
        out[c]            = win ? 1.0f : 0.0f;
        out[NUM_COLS + c] = win ? vc   : 0.0f;
    }
}

// ---------------------------------------------------------------------------
extern "C" void kernel_launch(void* const* d_in, const int* in_sizes, int n_in,
                              void* d_out, int out_size) {
    const float* inp   = nullptr;
    const float* conn  = nullptr;
    const float* boost = nullptr;
    for (int i = 0; i < n_in; i++) {
        if (in_sizes[i] == INPUT_SIZE)      inp   = (const float*)d_in[i];
        else if (in_sizes[i] == NUM_COLS)   boost = (const float*)d_in[i];
        else                                conn  = (const float*)d_in[i];
    }
    float* out = (float*)d_out;
    (void)out_size; (void)n_in;

    fused_kernel<<<NBLOCKS, THREADS>>>(inp, conn, boost);
    topk_kernel<<<NUM_COLS / 8, 256>>>(out);
}